// round 5
// baseline (speedup 1.0000x reference)
#include <cuda_runtime.h>
#include <cuda_fp16.h>
#include <cstdint>

#define L_SEQ 1024
#define BATCH_BS 8
#define EMB 512
#define O3 1536
#define NB 64            // BATCH_BS * NH

// Scratch (device globals)
__device__ __half g_Q[(size_t)NB * L_SEQ * 64];       // 8 MB
__device__ __half g_K[(size_t)NB * L_SEQ * 64];       // 8 MB
__device__ float  g_V[(size_t)NB * L_SEQ * 64];       // 16 MB
__device__ __half g_E[(size_t)NB * L_SEQ * L_SEQ];    // 134 MB, exp(scores) fp16
__device__ float  g_Zp[8 * NB * L_SEQ];               // per-keytile Z partials
__device__ float  g_R[NB * L_SEQ];                    // 1/Z
__device__ float  g_W[NB * L_SEQ];                    // attn weights (col sums)

// ---------------------------------------------------------------------------
// helpers
// ---------------------------------------------------------------------------
__device__ __forceinline__ uint32_t f22h2(float lo, float hi) {
    __half2 h = __floats2half2_rn(lo, hi);
    return reinterpret_cast<uint32_t&>(h);
}
__device__ __forceinline__ uint32_t smem_u32(const void* p) {
    return (uint32_t)__cvta_generic_to_shared(p);
}
__device__ __forceinline__ void ldsm4(uint32_t& r0, uint32_t& r1,
                                      uint32_t& r2, uint32_t& r3,
                                      const __half* p) {
    uint32_t addr = smem_u32(p);
    asm volatile("ldmatrix.sync.aligned.m8n8.x4.shared.b16 {%0,%1,%2,%3}, [%4];"
                 : "=r"(r0), "=r"(r1), "=r"(r2), "=r"(r3) : "r"(addr));
}
__device__ __forceinline__ void mma_f16(float* d, const uint32_t* a, const uint32_t* b) {
    asm volatile(
        "mma.sync.aligned.m16n8k16.row.col.f32.f16.f16.f32 "
        "{%0,%1,%2,%3}, {%4,%5,%6,%7}, {%8,%9}, {%0,%1,%2,%3};\n"
        : "+f"(d[0]), "+f"(d[1]), "+f"(d[2]), "+f"(d[3])
        : "r"(a[0]), "r"(a[1]), "r"(a[2]), "r"(a[3]), "r"(b[0]), "r"(b[1]));
}

// ---------------------------------------------------------------------------
// K1: QKV projection, fp16 mma.sync, NT, software-pipelined global loads.
// C = emb[8192,512] @ W[1536,512]^T + bias; scatters to g_Q/g_K (h), g_V (f).
// ---------------------------------------------------------------------------
#define SA 40
__global__ void __launch_bounds__(256) k1_qkv(
    const float* __restrict__ A, const float* __restrict__ Wt,
    const float* __restrict__ bias)
{
    __shared__ __half As[128 * SA];
    __shared__ __half Bs[128 * SA];

    const int tid  = threadIdx.x;
    const int warp = tid >> 5;
    const int lane = tid & 31;
    const int g = lane >> 2, t = lane & 3;
    const int wm0 = (warp >> 2) * 64;
    const int wn0 = (warp & 3) * 32;
    const int m0 = blockIdx.y * 128;
    const int n0 = blockIdx.x * 128;

    const int lrow = tid >> 1;
    const int lk   = (tid & 1) * 16;
    const float* ap = A  + (size_t)(m0 + lrow) * EMB + lk;
    const float* bp = Wt + (size_t)(n0 + lrow) * EMB + lk;

    const int lm = lane & 15;
    const int lc = (lane >> 4) * 8;

    float acc[4][4][4];
#pragma unroll
    for (int i = 0; i < 4; i++)
#pragma unroll
        for (int j = 0; j < 4; j++)
#pragma unroll
            for (int c = 0; c < 4; c++) acc[i][j][c] = 0.0f;

    // prologue load
    float4 av[4], bv[4];
#pragma unroll
    for (int j = 0; j < 4; j++) {
        av[j] = *(const float4*)(ap + 4 * j);
        bv[j] = *(const float4*)(bp + 4 * j);
    }

    for (int k0 = 0; k0 < EMB; k0 += 32) {
        __syncthreads();   // previous stage fully consumed
        *(uint4*)(As + lrow * SA + lk) =
            make_uint4(f22h2(av[0].x, av[0].y), f22h2(av[0].z, av[0].w),
                       f22h2(av[1].x, av[1].y), f22h2(av[1].z, av[1].w));
        *(uint4*)(As + lrow * SA + lk + 8) =
            make_uint4(f22h2(av[2].x, av[2].y), f22h2(av[2].z, av[2].w),
                       f22h2(av[3].x, av[3].y), f22h2(av[3].z, av[3].w));
        *(uint4*)(Bs + lrow * SA + lk) =
            make_uint4(f22h2(bv[0].x, bv[0].y), f22h2(bv[0].z, bv[0].w),
                       f22h2(bv[1].x, bv[1].y), f22h2(bv[1].z, bv[1].w));
        *(uint4*)(Bs + lrow * SA + lk + 8) =
            make_uint4(f22h2(bv[2].x, bv[2].y), f22h2(bv[2].z, bv[2].w),
                       f22h2(bv[3].x, bv[3].y), f22h2(bv[3].z, bv[3].w));
        __syncthreads();

        // prefetch next stage while mma runs
        if (k0 + 32 < EMB) {
#pragma unroll
            for (int j = 0; j < 4; j++) {
                av[j] = *(const float4*)(ap + k0 + 32 + 4 * j);
                bv[j] = *(const float4*)(bp + k0 + 32 + 4 * j);
            }
        }

#pragma unroll
        for (int kk = 0; kk < 32; kk += 16) {
            uint32_t af[4][4];
#pragma unroll
            for (int im = 0; im < 4; im++)
                ldsm4(af[im][0], af[im][1], af[im][2], af[im][3],
                      As + (wm0 + im * 16 + lm) * SA + kk + lc);
            uint32_t br0[4], br1[4];
            ldsm4(br0[0], br0[1], br0[2], br0[3], Bs + (wn0 +      lm) * SA + kk + lc);
            ldsm4(br1[0], br1[1], br1[2], br1[3], Bs + (wn0 + 16 + lm) * SA + kk + lc);
            uint32_t bf[4][2] = {{br0[0], br0[2]}, {br0[1], br0[3]},
                                 {br1[0], br1[2]}, {br1[1], br1[3]}};
#pragma unroll
            for (int im = 0; im < 4; im++)
#pragma unroll
                for (int in = 0; in < 4; in++)
                    mma_f16(acc[im][in], af[im], bf[in]);
        }
    }

    // Epilogue: +bias, scatter to g_Q / g_K (half) and g_V (float), [B][l][d].
#pragma unroll
    for (int im = 0; im < 4; im++) {
        const int r0 = m0 + wm0 + im * 16 + g;
#pragma unroll
        for (int in = 0; in < 4; in++) {
            const int c   = n0 + wn0 + in * 8 + 2 * t;
            const int h   = c / 192;
            const int rem = c - h * 192;
            const int sect = rem >> 6;
            const int d    = rem & 63;
            const float b0 = __ldg(bias + c), b1 = __ldg(bias + c + 1);
#pragma unroll
            for (int hf = 0; hf < 2; hf++) {
                const int r = r0 + hf * 8;
                const int l = r >> 3, bb = r & 7;
                const size_t off = ((size_t)(bb * 8 + h) << 16) + l * 64 + d;
                const float v0 = acc[im][in][2 * hf    ] + b0;
                const float v1 = acc[im][in][2 * hf + 1] + b1;
                if (sect == 0) {
                    *(uint32_t*)(g_Q + off) = f22h2(v0, v1);
                } else if (sect == 1) {
                    *(uint32_t*)(g_K + off) = f22h2(v0, v1);
                } else {
                    *(float2*)(g_V + off) = make_float2(v0, v1);
                }
            }
        }
    }
}

// ---------------------------------------------------------------------------
// K2: scores S = Q @ K^T per B, tile 128x128, d=64 fully in SMEM.
// Stores E = exp(0.125*S) as fp16, and per-keytile row-sum partials g_Zp
// (no atomics: each (n0-tile, B) owns its partial slot).
// ---------------------------------------------------------------------------
#define SQ 72
__global__ void __launch_bounds__(256) k2_scores()
{
    __shared__ __half Qs[128 * SQ];
    __shared__ __half Ks[128 * SQ];
    __shared__ float  zsh[128];

    const int tid  = threadIdx.x;
    const int warp = tid >> 5;
    const int lane = tid & 31;
    const int g = lane >> 2, t = lane & 3;
    const int wm0 = (warp >> 2) * 64;
    const int wn0 = (warp & 3) * 32;

    const int B   = blockIdx.z;
    const int n0t = blockIdx.x;
    const int n0  = n0t * 128;          // keys
    const int m0  = blockIdx.y * 128;   // queries

    const __half* qg = g_Q + ((size_t)B << 16) + (size_t)m0 * 64;
    const __half* kg = g_K + ((size_t)B << 16) + (size_t)n0 * 64;

    if (tid < 128) zsh[tid] = 0.0f;

#pragma unroll
    for (int j = 0; j < 4; j++) {
        const int idx = tid + j * 256;
        const int row = idx >> 3;
        const int ch  = (idx & 7) * 8;
        *(uint4*)(Qs + row * SQ + ch) = *(const uint4*)(qg + row * 64 + ch);
        *(uint4*)(Ks + row * SQ + ch) = *(const uint4*)(kg + row * 64 + ch);
    }
    __syncthreads();

    const int lm = lane & 15;
    const int lc = (lane >> 4) * 8;

    float acc[4][4][4];
#pragma unroll
    for (int i = 0; i < 4; i++)
#pragma unroll
        for (int j = 0; j < 4; j++)
#pragma unroll
            for (int c = 0; c < 4; c++) acc[i][j][c] = 0.0f;

#pragma unroll
    for (int kk = 0; kk < 64; kk += 16) {
        uint32_t af[4][4];
#pragma unroll
        for (int im = 0; im < 4; im++)
            ldsm4(af[im][0], af[im][1], af[im][2], af[im][3],
                  Qs + (wm0 + im * 16 + lm) * SQ + kk + lc);
        uint32_t br0[4], br1[4];
        ldsm4(br0[0], br0[1], br0[2], br0[3], Ks + (wn0 +      lm) * SQ + kk + lc);
        ldsm4(br1[0], br1[1], br1[2], br1[3], Ks + (wn0 + 16 + lm) * SQ + kk + lc);
        uint32_t bf[4][2] = {{br0[0], br0[2]}, {br0[1], br0[3]},
                             {br1[0], br1[2]}, {br1[1], br1[3]}};
#pragma unroll
        for (int im = 0; im < 4; im++)
#pragma unroll
            for (int in = 0; in < 4; in++)
                mma_f16(acc[im][in], af[im], bf[in]);
    }

    // Epilogue: exp, store fp16 E, per-row partial sums into smem then g_Zp.
    const size_t ebase = ((size_t)B << 20);
#pragma unroll
    for (int im = 0; im < 4; im++) {
#pragma unroll
        for (int hf = 0; hf < 2; hf++) {
            const int rloc = wm0 + im * 16 + g + hf * 8;
            const int row  = m0 + rloc;
            float rp = 0.0f;
#pragma unroll
            for (int in = 0; in < 4; in++) {
                const float e0 = __expf(acc[im][in][2 * hf    ] * 0.125f);
                const float e1 = __expf(acc[im][in][2 * hf + 1] * 0.125f);
                rp += e0 + e1;
                *(uint32_t*)(g_E + ebase + (size_t)row * 1024
                             + n0 + wn0 + in * 8 + 2 * t) = f22h2(e0, e1);
            }
            rp += __shfl_xor_sync(0xffffffffu, rp, 1);
            rp += __shfl_xor_sync(0xffffffffu, rp, 2);
            if (t == 0)
                atomicAdd(&zsh[rloc], rp);   // 4 warps share each row: smem atomic
        }
    }
    __syncthreads();
    if (tid < 128)
        g_Zp[(n0t * NB + B) * 1024 + m0 + tid] = zsh[tid];
}

// ---------------------------------------------------------------------------
// KZ: reduce 8 partials -> R = 1/Z
// ---------------------------------------------------------------------------
__global__ void kz_recip() {
    const int B = blockIdx.x;
    const int l = threadIdx.x;
    float s = 0.0f;
#pragma unroll
    for (int n = 0; n < 8; n++)
        s += g_Zp[(n * NB + B) * 1024 + l];
    g_R[B * 1024 + l] = 1.0f / s;
}

// ---------------------------------------------------------------------------
// K3: W[B][m'] = sum_l E[B][l][m'] * R[B][l]   (fp16 E, DRAM-bound)
// grid (8 coltiles, 64 B), 256 thr = 64 colpairs x 4 rowgroups of 256 rows.
// ---------------------------------------------------------------------------
__global__ void __launch_bounds__(256) k3_colsum()
{
    const int B   = blockIdx.y;
    const int m0  = blockIdx.x * 128;
    const int tid = threadIdx.x;
    const int cp  = tid & 63;        // column pair
    const int rg  = tid >> 6;        // 0..3

    const __half* ep = g_E + ((size_t)B << 20) + (size_t)rg * 256 * 1024 + m0 + cp * 2;
    const float*  rp = g_R + B * 1024 + rg * 256;

    float a0 = 0.0f, a1 = 0.0f;
#pragma unroll 8
    for (int l = 0; l < 256; l++) {
        const float2 e = __half22float2(*(const __half2*)(ep + (size_t)l * 1024));
        const float r = rp[l];
        a0 = fmaf(e.x, r, a0);
        a1 = fmaf(e.y, r, a1);
    }

    __shared__ float2 sh[256];
    sh[tid] = make_float2(a0, a1);
    __syncthreads();
    if (tid < 64) {
        float2 s = sh[tid];
#pragma unroll
        for (int gq = 1; gq < 4; gq++) {
            s.x += sh[gq * 64 + tid].x;
            s.y += sh[gq * 64 + tid].y;
        }
        *(float2*)(g_W + B * 1024 + m0 + tid * 2) = s;
    }
}

// ---------------------------------------------------------------------------
// K4: out_v[B][d] = sum_m W[B][m] * V[B][m][d]; GroupNorm over d=64 per B.
// ---------------------------------------------------------------------------
__global__ void __launch_bounds__(512) k4_out(
    const float* __restrict__ gw, const float* __restrict__ gb,
    float* __restrict__ out)
{
    const int B  = blockIdx.x;
    const int bb = B >> 3, hh = B & 7;
    const int tid = threadIdx.x;
    const int d = tid & 63, mg = tid >> 6;
    const float* vptr = g_V + ((size_t)B << 16) + d;
    const float* wp = g_W + B * 1024;

    float acc = 0.0f;
#pragma unroll 4
    for (int m = mg; m < 1024; m += 8)
        acc = fmaf(wp[m], vptr[m * 64], acc);

    __shared__ float part[8][64];
    __shared__ float vout[64];
    __shared__ float s_mean, s_rstd;
    part[mg][d] = acc;
    __syncthreads();

    if (tid < 64) {
        float s = 0.0f;
#pragma unroll
        for (int g = 0; g < 8; g++) s += part[g][tid];
        vout[tid] = s;
    }
    __syncthreads();

    if (tid < 32) {
        float x1 = vout[tid], x2 = vout[tid + 32];
        float s  = x1 + x2;
        float sq = x1 * x1 + x2 * x2;
#pragma unroll
        for (int o = 16; o > 0; o >>= 1) {
            s  += __shfl_down_sync(0xffffffffu, s, o);
            sq += __shfl_down_sync(0xffffffffu, sq, o);
        }
        if (tid == 0) {
            float mean = s * (1.0f / 64.0f);
            float var  = sq * (1.0f / 64.0f) - mean * mean;
            s_mean = mean;
            s_rstd = rsqrtf(var + 1e-5f);
        }
    }
    __syncthreads();

    if (tid < 64)
        out[bb * 512 + hh * 64 + tid] =
            (vout[tid] - s_mean) * s_rstd * gw[hh] + gb[hh];
}

// ---------------------------------------------------------------------------
// Launcher (graph-capturable: kernel launches only)
// ---------------------------------------------------------------------------
extern "C" void kernel_launch(void* const* d_in, const int* in_sizes, int n_in,
                              void* d_out, int out_size)
{
    (void)in_sizes; (void)n_in; (void)out_size;
    const float* emb = (const float*)d_in[0];
    const float* Wq  = (const float*)d_in[1];
    const float* bq  = (const float*)d_in[2];
    const float* gw  = (const float*)d_in[3];
    const float* gb  = (const float*)d_in[4];
    float* out = (float*)d_out;

    k1_qkv   <<<dim3(12, 64), 256>>>(emb, Wq, bq);
    k2_scores<<<dim3(8, 8, 64), 256>>>();
    kz_recip <<<64, 1024>>>();
    k3_colsum<<<dim3(8, 64), 256>>>();
    k4_out   <<<64, 512>>>(gw, gb, out);
}

// round 6
// speedup vs baseline: 1.3095x; 1.3095x over previous
#include <cuda_runtime.h>
#include <cuda_fp16.h>
#include <cstdint>

#define L_SEQ 1024
#define BATCH_BS 8
#define EMB 512
#define O3 1536
#define NB 64            // BATCH_BS * NH

// Scratch (device globals)
__device__ __half g_Ah[(size_t)8192 * EMB];       // emb as fp16, 8 MB
__device__ __half g_Bh[(size_t)O3 * EMB];         // W_qkv as fp16, 1.5 MB
__device__ __half g_Q[(size_t)NB * L_SEQ * 64];   // 8 MB
__device__ __half g_K[(size_t)NB * L_SEQ * 64];   // 8 MB
__device__ float  g_V[(size_t)NB * L_SEQ * 64];   // 16 MB
__device__ float  g_Z[NB * L_SEQ];                // row sums -> reciprocals
__device__ float  g_W[NB * L_SEQ];                // attn weights (col sums)

// ---------------------------------------------------------------------------
// helpers
// ---------------------------------------------------------------------------
__device__ __forceinline__ uint32_t f22h2(float lo, float hi) {
    __half2 h = __floats2half2_rn(lo, hi);
    return reinterpret_cast<uint32_t&>(h);
}
__device__ __forceinline__ uint32_t smem_u32(const void* p) {
    return (uint32_t)__cvta_generic_to_shared(p);
}
__device__ __forceinline__ void ldsm4(uint32_t& r0, uint32_t& r1,
                                      uint32_t& r2, uint32_t& r3,
                                      const __half* p) {
    uint32_t addr = smem_u32(p);
    asm volatile("ldmatrix.sync.aligned.m8n8.x4.shared.b16 {%0,%1,%2,%3}, [%4];"
                 : "=r"(r0), "=r"(r1), "=r"(r2), "=r"(r3) : "r"(addr));
}
__device__ __forceinline__ void mma_f16(float* d, const uint32_t* a, const uint32_t* b) {
    asm volatile(
        "mma.sync.aligned.m16n8k16.row.col.f32.f16.f16.f32 "
        "{%0,%1,%2,%3}, {%4,%5,%6,%7}, {%8,%9}, {%0,%1,%2,%3};\n"
        : "+f"(d[0]), "+f"(d[1]), "+f"(d[2]), "+f"(d[3])
        : "r"(a[0]), "r"(a[1]), "r"(a[2]), "r"(a[3]), "r"(b[0]), "r"(b[1]));
}

// ---------------------------------------------------------------------------
// KC: one-time fp32 -> fp16 convert of emb (4.19M f) and W_qkv (0.79M f).
// Also zeroes Z and W (accumulated by atomics each replay).
// grid 1216 x 1024 covers 1245184 float4s exactly.
// ---------------------------------------------------------------------------
__global__ void __launch_bounds__(1024) kcvt(
    const float* __restrict__ A, const float* __restrict__ B)
{
    const size_t i = (size_t)blockIdx.x * 1024 + threadIdx.x;
    if (i < 1048576) {
        const float4 v = ((const float4*)A)[i];
        ((uint2*)g_Ah)[i] = make_uint2(f22h2(v.x, v.y), f22h2(v.z, v.w));
    } else {
        const size_t j = i - 1048576;
        const float4 v = ((const float4*)B)[j];
        ((uint2*)g_Bh)[j] = make_uint2(f22h2(v.x, v.y), f22h2(v.z, v.w));
    }
    if (i < NB * L_SEQ) {
        g_Z[i] = 0.0f;
        g_W[i] = 0.0f;
    }
}

// ---------------------------------------------------------------------------
// K1: C = emb_h[8192,512] @ W_h[1536,512]^T + bias  (fp16 mma, NT)
// fp16 global inputs, double-buffered smem, ONE sync per k-stage.
// CTA 128x128, BK=32, 8 warps (2m x 4n), warp tile 64x32.
// Epilogue scatters to g_Q/g_K (fp16) and g_V (fp32) in [B][l][d] layout.
// ---------------------------------------------------------------------------
#define SA 40
__global__ void __launch_bounds__(256) k1_qkv(const float* __restrict__ bias)
{
    __shared__ __half As[2][128 * SA];
    __shared__ __half Bs[2][128 * SA];

    const int tid  = threadIdx.x;
    const int warp = tid >> 5;
    const int lane = tid & 31;
    const int g = lane >> 2, t = lane & 3;
    const int wm0 = (warp >> 2) * 64;
    const int wn0 = (warp & 3) * 32;
    const int m0 = blockIdx.y * 128;
    const int n0 = blockIdx.x * 128;

    const int lrow = tid >> 1;              // 0..127
    const int lk   = (tid & 1) * 16;        // 0 or 16 (halves)
    const __half* ap = g_Ah + (size_t)(m0 + lrow) * EMB + lk;
    const __half* bp = g_Bh + (size_t)(n0 + lrow) * EMB + lk;

    const int lm = lane & 15;
    const int lc = (lane >> 4) * 8;

    float acc[4][4][4];
#pragma unroll
    for (int i = 0; i < 4; i++)
#pragma unroll
        for (int j = 0; j < 4; j++)
#pragma unroll
            for (int c = 0; c < 4; c++) acc[i][j][c] = 0.0f;

    // prologue: stage 0 -> buf 0
    uint4 a0 = *(const uint4*)(ap);
    uint4 a1 = *(const uint4*)(ap + 8);
    uint4 b0 = *(const uint4*)(bp);
    uint4 b1 = *(const uint4*)(bp + 8);
    *(uint4*)(As[0] + lrow * SA + lk)     = a0;
    *(uint4*)(As[0] + lrow * SA + lk + 8) = a1;
    *(uint4*)(Bs[0] + lrow * SA + lk)     = b0;
    *(uint4*)(Bs[0] + lrow * SA + lk + 8) = b1;

#pragma unroll 4
    for (int s = 0; s < 16; s++) {
        // prefetch next stage from gmem
        if (s < 15) {
            const int nk = (s + 1) * 32;
            a0 = *(const uint4*)(ap + nk);
            a1 = *(const uint4*)(ap + nk + 8);
            b0 = *(const uint4*)(bp + nk);
            b1 = *(const uint4*)(bp + nk + 8);
        }
        __syncthreads();   // buf[s&1] stores complete; prior reads complete
        const __half* Ab = As[s & 1];
        const __half* Bb = Bs[s & 1];
#pragma unroll
        for (int kk = 0; kk < 32; kk += 16) {
            uint32_t af[4][4];
#pragma unroll
            for (int im = 0; im < 4; im++)
                ldsm4(af[im][0], af[im][1], af[im][2], af[im][3],
                      Ab + (wm0 + im * 16 + lm) * SA + kk + lc);
            uint32_t br0[4], br1[4];
            ldsm4(br0[0], br0[1], br0[2], br0[3], Bb + (wn0 +      lm) * SA + kk + lc);
            ldsm4(br1[0], br1[1], br1[2], br1[3], Bb + (wn0 + 16 + lm) * SA + kk + lc);
            uint32_t bf[4][2] = {{br0[0], br0[2]}, {br0[1], br0[3]},
                                 {br1[0], br1[2]}, {br1[1], br1[3]}};
#pragma unroll
            for (int im = 0; im < 4; im++)
#pragma unroll
                for (int in = 0; in < 4; in++)
                    mma_f16(acc[im][in], af[im], bf[in]);
        }
        // store next stage into the other buffer (disjoint from current reads)
        if (s < 15) {
            __half* An = As[(s + 1) & 1];
            __half* Bn = Bs[(s + 1) & 1];
            *(uint4*)(An + lrow * SA + lk)     = a0;
            *(uint4*)(An + lrow * SA + lk + 8) = a1;
            *(uint4*)(Bn + lrow * SA + lk)     = b0;
            *(uint4*)(Bn + lrow * SA + lk + 8) = b1;
        }
    }

    // Epilogue: +bias, scatter to g_Q / g_K (half) and g_V (float), [B][l][d].
#pragma unroll
    for (int im = 0; im < 4; im++) {
        const int r0 = m0 + wm0 + im * 16 + g;
#pragma unroll
        for (int in = 0; in < 4; in++) {
            const int c   = n0 + wn0 + in * 8 + 2 * t;
            const int h   = c / 192;
            const int rem = c - h * 192;
            const int sect = rem >> 6;
            const int d    = rem & 63;
            const float b0f = __ldg(bias + c), b1f = __ldg(bias + c + 1);
#pragma unroll
            for (int hf = 0; hf < 2; hf++) {
                const int r = r0 + hf * 8;
                const int l = r >> 3, bb = r & 7;
                const size_t off = ((size_t)(bb * 8 + h) << 16) + l * 64 + d;
                const float v0 = acc[im][in][2 * hf    ] + b0f;
                const float v1 = acc[im][in][2 * hf + 1] + b1f;
                if (sect == 0) {
                    *(uint32_t*)(g_Q + off) = f22h2(v0, v1);
                } else if (sect == 1) {
                    *(uint32_t*)(g_K + off) = f22h2(v0, v1);
                } else {
                    *(float2*)(g_V + off) = make_float2(v0, v1);
                }
            }
        }
    }
}

// ---------------------------------------------------------------------------
// K2: scores S = Q @ K^T per B, tile 128x128, d=64 fully in SMEM (no k-loop).
// PASS2=false: Z[row] += sum over cols of exp(0.125*S)        (row sums)
// PASS2=true : W[col] += sum over rows of exp(0.125*S)/Z[row] (col sums)
// ---------------------------------------------------------------------------
#define SQ 72
template<bool PASS2>
__global__ void __launch_bounds__(256) k2_attn()
{
    __shared__ __half Qs[128 * SQ];
    __shared__ __half Ks[128 * SQ];

    const int tid  = threadIdx.x;
    const int warp = tid >> 5;
    const int lane = tid & 31;
    const int g = lane >> 2, t = lane & 3;
    const int wm0 = (warp >> 2) * 64;
    const int wn0 = (warp & 3) * 32;

    const int B  = blockIdx.z;
    const int n0 = blockIdx.x * 128;    // keys
    const int m0 = blockIdx.y * 128;    // queries

    const __half* qg = g_Q + ((size_t)B << 16) + (size_t)m0 * 64;
    const __half* kg = g_K + ((size_t)B << 16) + (size_t)n0 * 64;

#pragma unroll
    for (int j = 0; j < 4; j++) {
        const int idx = tid + j * 256;
        const int row = idx >> 3;
        const int ch  = (idx & 7) * 8;
        *(uint4*)(Qs + row * SQ + ch) = *(const uint4*)(qg + row * 64 + ch);
        *(uint4*)(Ks + row * SQ + ch) = *(const uint4*)(kg + row * 64 + ch);
    }
    __syncthreads();

    const int lm = lane & 15;
    const int lc = (lane >> 4) * 8;

    float acc[4][4][4];
#pragma unroll
    for (int i = 0; i < 4; i++)
#pragma unroll
        for (int j = 0; j < 4; j++)
#pragma unroll
            for (int c = 0; c < 4; c++) acc[i][j][c] = 0.0f;

#pragma unroll
    for (int kk = 0; kk < 64; kk += 16) {
        uint32_t af[4][4];
#pragma unroll
        for (int im = 0; im < 4; im++)
            ldsm4(af[im][0], af[im][1], af[im][2], af[im][3],
                  Qs + (wm0 + im * 16 + lm) * SQ + kk + lc);
        uint32_t br0[4], br1[4];
        ldsm4(br0[0], br0[1], br0[2], br0[3], Ks + (wn0 +      lm) * SQ + kk + lc);
        ldsm4(br1[0], br1[1], br1[2], br1[3], Ks + (wn0 + 16 + lm) * SQ + kk + lc);
        uint32_t bf[4][2] = {{br0[0], br0[2]}, {br0[1], br0[3]},
                             {br1[0], br1[2]}, {br1[1], br1[3]}};
#pragma unroll
        for (int im = 0; im < 4; im++)
#pragma unroll
            for (int in = 0; in < 4; in++)
                mma_f16(acc[im][in], af[im], bf[in]);
    }

    if (!PASS2) {
        // row sums -> g_Z
#pragma unroll
        for (int im = 0; im < 4; im++) {
#pragma unroll
            for (int hf = 0; hf < 2; hf++) {
                const int row = m0 + wm0 + im * 16 + g + hf * 8;
                float rp = 0.0f;
#pragma unroll
                for (int in = 0; in < 4; in++)
                    rp += __expf(acc[im][in][2 * hf] * 0.125f)
                        + __expf(acc[im][in][2 * hf + 1] * 0.125f);
                rp += __shfl_xor_sync(0xffffffffu, rp, 1);
                rp += __shfl_xor_sync(0xffffffffu, rp, 2);
                if ((lane & 3) == 0)
                    atomicAdd(&g_Z[B * 1024 + row], rp);
            }
        }
    } else {
        // col sums of exp * (1/Z[row]) -> g_W
        float ca[4][2];
#pragma unroll
        for (int in = 0; in < 4; in++) { ca[in][0] = 0.0f; ca[in][1] = 0.0f; }
#pragma unroll
        for (int im = 0; im < 4; im++) {
            const int rowg = m0 + wm0 + im * 16 + g;
            const float rA = __ldg(&g_Z[B * 1024 + rowg]);
            const float rB = __ldg(&g_Z[B * 1024 + rowg + 8]);
#pragma unroll
            for (int in = 0; in < 4; in++) {
                ca[in][0] += __expf(acc[im][in][0] * 0.125f) * rA
                           + __expf(acc[im][in][2] * 0.125f) * rB;
                ca[in][1] += __expf(acc[im][in][1] * 0.125f) * rA
                           + __expf(acc[im][in][3] * 0.125f) * rB;
            }
        }
#pragma unroll
        for (int in = 0; in < 4; in++) {
#pragma unroll
            for (int s = 0; s < 2; s++) {
                float v = ca[in][s];
                v += __shfl_xor_sync(0xffffffffu, v, 4);
                v += __shfl_xor_sync(0xffffffffu, v, 8);
                v += __shfl_xor_sync(0xffffffffu, v, 16);
                if (lane < 4)
                    atomicAdd(&g_W[B * 1024 + n0 + wn0 + in * 8 + 2 * t + s], v);
            }
        }
    }
}

// ---------------------------------------------------------------------------
// K2b: Z -> 1/Z
// ---------------------------------------------------------------------------
__global__ void k_zrecip() {
    const int i = blockIdx.x * 1024 + threadIdx.x;
    g_Z[i] = 1.0f / g_Z[i];
}

// ---------------------------------------------------------------------------
// K4: out_v[B][d] = sum_m W[B][m] * V[B][m][d]; GroupNorm over d=64 per B.
// ---------------------------------------------------------------------------
__global__ void __launch_bounds__(512) k4_out(
    const float* __restrict__ gw, const float* __restrict__ gb,
    float* __restrict__ out)
{
    const int B  = blockIdx.x;
    const int bb = B >> 3, hh = B & 7;
    const int tid = threadIdx.x;
    const int d = tid & 63, mg = tid >> 6;
    const float* vptr = g_V + ((size_t)B << 16) + d;
    const float* wp = g_W + B * 1024;

    float acc = 0.0f;
#pragma unroll 4
    for (int m = mg; m < 1024; m += 8)
        acc = fmaf(wp[m], vptr[m * 64], acc);

    __shared__ float part[8][64];
    __shared__ float vout[64];
    __shared__ float s_mean, s_rstd;
    part[mg][d] = acc;
    __syncthreads();

    if (tid < 64) {
        float s = 0.0f;
#pragma unroll
        for (int g = 0; g < 8; g++) s += part[g][tid];
        vout[tid] = s;
    }
    __syncthreads();

    if (tid < 32) {
        float x1 = vout[tid], x2 = vout[tid + 32];
        float s  = x1 + x2;
        float sq = x1 * x1 + x2 * x2;
#pragma unroll
        for (int o = 16; o > 0; o >>= 1) {
            s  += __shfl_down_sync(0xffffffffu, s, o);
            sq += __shfl_down_sync(0xffffffffu, sq, o);
        }
        if (tid == 0) {
            float mean = s * (1.0f / 64.0f);
            float var  = sq * (1.0f / 64.0f) - mean * mean;
            s_mean = mean;
            s_rstd = rsqrtf(var + 1e-5f);
        }
    }
    __syncthreads();

    if (tid < 64)
        out[bb * 512 + hh * 64 + tid] =
            (vout[tid] - s_mean) * s_rstd * gw[hh] + gb[hh];
}

// ---------------------------------------------------------------------------
// Launcher (graph-capturable)
// ---------------------------------------------------------------------------
extern "C" void kernel_launch(void* const* d_in, const int* in_sizes, int n_in,
                              void* d_out, int out_size)
{
    (void)in_sizes; (void)n_in; (void)out_size;
    const float* emb = (const float*)d_in[0];
    const float* Wq  = (const float*)d_in[1];
    const float* bq  = (const float*)d_in[2];
    const float* gw  = (const float*)d_in[3];
    const float* gb  = (const float*)d_in[4];
    float* out = (float*)d_out;

    kcvt     <<<1216, 1024>>>(emb, Wq);
    k1_qkv   <<<dim3(12, 64), 256>>>(bq);
    k2_attn<false><<<dim3(8, 8, 64), 256>>>();
    k_zrecip <<<64, 1024>>>();
    k2_attn<true> <<<dim3(8, 8, 64), 256>>>();
    k4_out   <<<64, 512>>>(gw, gb, out);
}